// round 1
// baseline (speedup 1.0000x reference)
#include <cuda_runtime.h>
#include <cstdint>
#include <cstddef>

// Problem constants
#define Bc 8
#define Sc 1024
#define Dc 1024
#define Hc 16
#define DKc 64
#define Mrows (Bc*Sc)          // 8192

// Scratch (allocation-free rule: __device__ globals)
__device__ float g_Q[Bc*Sc*Dc];
__device__ float g_K[Bc*Sc*Dc];
__device__ float g_V[Bc*Sc*Dc];
__device__ float g_ctx[Bc*Sc*Dc];

// ---------------------------------------------------------------------------
// Projection GEMM: C[M,N] = alpha * (A[M,K] @ W[N,K]^T + bias[N])
// Tile 128x128, BK=8, 256 threads, 8x8 per-thread micro-tile.
// ---------------------------------------------------------------------------
__global__ __launch_bounds__(256) void proj_gemm(
    const float* __restrict__ A, const float* __restrict__ W,
    const float* __restrict__ bias, float* __restrict__ C,
    int Kdim, int Ndim, float alpha)
{
    __shared__ float As[8][128];
    __shared__ float Bs[8][128];
    const int bm = blockIdx.y * 128;
    const int bn = blockIdx.x * 128;
    const int tid = threadIdx.x;
    const int tx = tid & 15, ty = tid >> 4;

    float acc[8][8];
    #pragma unroll
    for (int i = 0; i < 8; i++)
        #pragma unroll
        for (int j = 0; j < 8; j++) acc[i][j] = 0.f;

    const int m_l = tid >> 1;        // 0..127
    const int kq  = tid & 1;         // 0..1  (two float4 per 8-wide k slab)
    const float* Arow = A + (size_t)(bm + m_l) * Kdim + kq * 4;
    const float* Wrow = W + (size_t)(bn + m_l) * Kdim + kq * 4;

    for (int k0 = 0; k0 < Kdim; k0 += 8) {
        float4 av = *(const float4*)(Arow + k0);
        float4 wv = *(const float4*)(Wrow + k0);
        __syncthreads();
        As[kq*4+0][m_l] = av.x; As[kq*4+1][m_l] = av.y;
        As[kq*4+2][m_l] = av.z; As[kq*4+3][m_l] = av.w;
        Bs[kq*4+0][m_l] = wv.x; Bs[kq*4+1][m_l] = wv.y;
        Bs[kq*4+2][m_l] = wv.z; Bs[kq*4+3][m_l] = wv.w;
        __syncthreads();
        #pragma unroll
        for (int kk = 0; kk < 8; kk++) {
            float4 a0 = *(const float4*)&As[kk][ty*8];
            float4 a1 = *(const float4*)&As[kk][ty*8+4];
            float4 b0 = *(const float4*)&Bs[kk][tx*8];
            float4 b1 = *(const float4*)&Bs[kk][tx*8+4];
            float a[8] = {a0.x,a0.y,a0.z,a0.w,a1.x,a1.y,a1.z,a1.w};
            float b[8] = {b0.x,b0.y,b0.z,b0.w,b1.x,b1.y,b1.z,b1.w};
            #pragma unroll
            for (int i = 0; i < 8; i++)
                #pragma unroll
                for (int j = 0; j < 8; j++)
                    acc[i][j] += a[i] * b[j];
        }
    }

    float bb[8];
    #pragma unroll
    for (int j = 0; j < 8; j++) bb[j] = bias[bn + tx*8 + j];
    #pragma unroll
    for (int i = 0; i < 8; i++) {
        float* crow = C + (size_t)(bm + ty*8 + i) * Ndim + bn + tx*8;
        float4 o0, o1;
        o0.x = alpha*(acc[i][0]+bb[0]); o0.y = alpha*(acc[i][1]+bb[1]);
        o0.z = alpha*(acc[i][2]+bb[2]); o0.w = alpha*(acc[i][3]+bb[3]);
        o1.x = alpha*(acc[i][4]+bb[4]); o1.y = alpha*(acc[i][5]+bb[5]);
        o1.z = alpha*(acc[i][6]+bb[6]); o1.w = alpha*(acc[i][7]+bb[7]);
        *(float4*)(crow)     = o0;
        *(float4*)(crow + 4) = o1;
    }
}

// ---------------------------------------------------------------------------
// Scores GEMM (per head): att[bh][q][k] = Qh[q,:] . Kh[k,:]  (scale folded in Q)
// Tile 128x128, K=64 (BK=8).
// ---------------------------------------------------------------------------
__global__ __launch_bounds__(256) void scores_gemm(
    const float* __restrict__ Q, const float* __restrict__ Km,
    float* __restrict__ att)
{
    const int bh = blockIdx.z;
    const int b  = bh >> 4;
    const int h  = bh & 15;
    const float* Aq = Q  + (size_t)b * Sc * Dc + h * DKc;   // row stride Dc
    const float* Bk = Km + (size_t)b * Sc * Dc + h * DKc;
    float* C = att + (size_t)bh * Sc * Sc;

    __shared__ float As[8][128];
    __shared__ float Bs[8][128];
    const int bm = blockIdx.y * 128;
    const int bn = blockIdx.x * 128;
    const int tid = threadIdx.x;
    const int tx = tid & 15, ty = tid >> 4;

    float acc[8][8];
    #pragma unroll
    for (int i = 0; i < 8; i++)
        #pragma unroll
        for (int j = 0; j < 8; j++) acc[i][j] = 0.f;

    const int m_l = tid >> 1;
    const int kq  = tid & 1;

    for (int k0 = 0; k0 < DKc; k0 += 8) {
        float4 av = *(const float4*)&Aq[(size_t)(bm + m_l) * Dc + k0 + kq*4];
        float4 bv = *(const float4*)&Bk[(size_t)(bn + m_l) * Dc + k0 + kq*4];
        __syncthreads();
        As[kq*4+0][m_l] = av.x; As[kq*4+1][m_l] = av.y;
        As[kq*4+2][m_l] = av.z; As[kq*4+3][m_l] = av.w;
        Bs[kq*4+0][m_l] = bv.x; Bs[kq*4+1][m_l] = bv.y;
        Bs[kq*4+2][m_l] = bv.z; Bs[kq*4+3][m_l] = bv.w;
        __syncthreads();
        #pragma unroll
        for (int kk = 0; kk < 8; kk++) {
            float4 a0 = *(const float4*)&As[kk][ty*8];
            float4 a1 = *(const float4*)&As[kk][ty*8+4];
            float4 b0 = *(const float4*)&Bs[kk][tx*8];
            float4 b1 = *(const float4*)&Bs[kk][tx*8+4];
            float a[8] = {a0.x,a0.y,a0.z,a0.w,a1.x,a1.y,a1.z,a1.w};
            float b[8] = {b0.x,b0.y,b0.z,b0.w,b1.x,b1.y,b1.z,b1.w};
            #pragma unroll
            for (int i = 0; i < 8; i++)
                #pragma unroll
                for (int j = 0; j < 8; j++)
                    acc[i][j] += a[i] * b[j];
        }
    }

    #pragma unroll
    for (int i = 0; i < 8; i++) {
        float* crow = C + (size_t)(bm + ty*8 + i) * Sc + bn + tx*8;
        *(float4*)(crow)     = make_float4(acc[i][0], acc[i][1], acc[i][2], acc[i][3]);
        *(float4*)(crow + 4) = make_float4(acc[i][4], acc[i][5], acc[i][6], acc[i][7]);
    }
}

// ---------------------------------------------------------------------------
// Softmax (in-place over att rows) with query-row masking.
// Masked rows -> exactly uniform 1/S (== softmax of constant -1e9 row).
// mask read as 4-byte nonzero test (covers float32 0/1 and int32 0/1).
// ---------------------------------------------------------------------------
__global__ __launch_bounds__(256) void softmax_kernel(
    float* __restrict__ att, const unsigned int* __restrict__ mask)
{
    const int row = blockIdx.x;           // bh*S + q
    const int q   = row & (Sc - 1);
    const int bh  = row >> 10;
    const int b   = bh >> 4;
    float* p = att + (size_t)row * Sc;
    const int tid = threadIdx.x;

    if (mask[b * Sc + q] != 0u) {
        const float u = 1.0f / (float)Sc;
        ((float4*)p)[tid] = make_float4(u, u, u, u);
        return;
    }

    __shared__ float sh[16];
    float4 x = ((const float4*)p)[tid];
    float mx = fmaxf(fmaxf(x.x, x.y), fmaxf(x.z, x.w));
    #pragma unroll
    for (int o = 16; o; o >>= 1) mx = fmaxf(mx, __shfl_xor_sync(0xffffffffu, mx, o));
    const int w = tid >> 5, l = tid & 31;
    if (l == 0) sh[w] = mx;
    __syncthreads();
    if (tid < 32) {
        float v = (l < 8) ? sh[l] : -3.4e38f;
        #pragma unroll
        for (int o = 4; o; o >>= 1) v = fmaxf(v, __shfl_xor_sync(0xffffffffu, v, o));
        if (l == 0) sh[8] = v;
    }
    __syncthreads();
    mx = sh[8];

    float e0 = __expf(x.x - mx), e1 = __expf(x.y - mx);
    float e2 = __expf(x.z - mx), e3 = __expf(x.w - mx);
    float s = e0 + e1 + e2 + e3;
    #pragma unroll
    for (int o = 16; o; o >>= 1) s += __shfl_xor_sync(0xffffffffu, s, o);
    if (l == 0) sh[w] = s;
    __syncthreads();
    if (tid < 32) {
        float v = (l < 8) ? sh[l] : 0.f;
        #pragma unroll
        for (int o = 4; o; o >>= 1) v += __shfl_xor_sync(0xffffffffu, v, o);
        if (l == 0) sh[9] = v;
    }
    __syncthreads();
    const float inv = 1.0f / sh[9];
    ((float4*)p)[tid] = make_float4(e0*inv, e1*inv, e2*inv, e3*inv);
}

// ---------------------------------------------------------------------------
// Context GEMM (per head): ctx[q, d] = sum_k att[q,k] * Vh[k,d]
// Tile 128(q) x 64(d), BK=16, 256 threads, 8x4 per-thread.
// ---------------------------------------------------------------------------
__global__ __launch_bounds__(256) void ctx_gemm(
    const float* __restrict__ att, const float* __restrict__ V,
    float* __restrict__ ctx)
{
    const int bh = blockIdx.z;
    const int b  = bh >> 4;
    const int h  = bh & 15;
    const float* A  = att + (size_t)bh * Sc * Sc;            // [S,S]
    const float* Vb = V   + (size_t)b * Sc * Dc + h * DKc;   // row stride Dc
    float* Cb       = ctx + (size_t)b * Sc * Dc + h * DKc;

    __shared__ float As[16][128];   // att chunk, k-major
    __shared__ float Bs[16][64];    // V chunk
    const int bm = blockIdx.y * 128;
    const int tid = threadIdx.x;
    const int tx = tid & 15, ty = tid >> 4;

    float acc[8][4];
    #pragma unroll
    for (int i = 0; i < 8; i++)
        #pragma unroll
        for (int j = 0; j < 4; j++) acc[i][j] = 0.f;

    for (int k0 = 0; k0 < Sc; k0 += 16) {
        // As: 128 m x 16 k = 512 float4-items (m=idx>>2, kq=idx&3), 2 per thread
        const int i0 = tid,       m0 = i0 >> 2, kq0 = i0 & 3;
        const int i1 = tid + 256, m1 = i1 >> 2, kq1 = i1 & 3;
        float4 a0v = *(const float4*)&A[(size_t)(bm + m0) * Sc + k0 + kq0*4];
        float4 a1v = *(const float4*)&A[(size_t)(bm + m1) * Sc + k0 + kq1*4];
        // Bs: 16 k x 64 n -> 256 float4-items: k=tid>>4, nq=tid&15
        const int kb = tid >> 4, nq = tid & 15;
        float4 bv = *(const float4*)&Vb[(size_t)(k0 + kb) * Dc + nq*4];
        __syncthreads();
        As[kq0*4+0][m0] = a0v.x; As[kq0*4+1][m0] = a0v.y;
        As[kq0*4+2][m0] = a0v.z; As[kq0*4+3][m0] = a0v.w;
        As[kq1*4+0][m1] = a1v.x; As[kq1*4+1][m1] = a1v.y;
        As[kq1*4+2][m1] = a1v.z; As[kq1*4+3][m1] = a1v.w;
        *(float4*)&Bs[kb][nq*4] = bv;
        __syncthreads();
        #pragma unroll
        for (int kk = 0; kk < 16; kk++) {
            float4 a0 = *(const float4*)&As[kk][ty*8];
            float4 a1 = *(const float4*)&As[kk][ty*8+4];
            float4 bq = *(const float4*)&Bs[kk][tx*4];
            float a[8] = {a0.x,a0.y,a0.z,a0.w,a1.x,a1.y,a1.z,a1.w};
            float bb[4] = {bq.x,bq.y,bq.z,bq.w};
            #pragma unroll
            for (int i = 0; i < 8; i++)
                #pragma unroll
                for (int j = 0; j < 4; j++)
                    acc[i][j] += a[i] * bb[j];
        }
    }

    #pragma unroll
    for (int i = 0; i < 8; i++) {
        *(float4*)&Cb[(size_t)(bm + ty*8 + i) * Dc + tx*4] =
            make_float4(acc[i][0], acc[i][1], acc[i][2], acc[i][3]);
    }
}

// ---------------------------------------------------------------------------
// Output GEMM: out[m,n] = sum_k concat(query,ctx)[m,k] * Wp[n,k] + bp[n]
// M=8192, N=1024, K=2048. Same 128x128x8 tiling.
// ---------------------------------------------------------------------------
__global__ __launch_bounds__(256) void out_gemm(
    const float* __restrict__ query, const float* __restrict__ ctx,
    const float* __restrict__ Wp, const float* __restrict__ bp,
    float* __restrict__ out)
{
    __shared__ float As[8][128];
    __shared__ float Bs[8][128];
    const int bm = blockIdx.y * 128;
    const int bn = blockIdx.x * 128;
    const int tid = threadIdx.x;
    const int tx = tid & 15, ty = tid >> 4;

    float acc[8][8];
    #pragma unroll
    for (int i = 0; i < 8; i++)
        #pragma unroll
        for (int j = 0; j < 8; j++) acc[i][j] = 0.f;

    const int m_l = tid >> 1;
    const int kq  = tid & 1;

    for (int k0 = 0; k0 < 2*Dc; k0 += 8) {
        const int kb = k0 + kq*4;
        const float* src = (kb < Dc)
            ? (query + (size_t)(bm + m_l) * Dc + kb)
            : (ctx   + (size_t)(bm + m_l) * Dc + (kb - Dc));
        float4 av = *(const float4*)src;
        float4 wv = *(const float4*)&Wp[(size_t)(bn + m_l) * (2*Dc) + kb];
        __syncthreads();
        As[kq*4+0][m_l] = av.x; As[kq*4+1][m_l] = av.y;
        As[kq*4+2][m_l] = av.z; As[kq*4+3][m_l] = av.w;
        Bs[kq*4+0][m_l] = wv.x; Bs[kq*4+1][m_l] = wv.y;
        Bs[kq*4+2][m_l] = wv.z; Bs[kq*4+3][m_l] = wv.w;
        __syncthreads();
        #pragma unroll
        for (int kk = 0; kk < 8; kk++) {
            float4 a0 = *(const float4*)&As[kk][ty*8];
            float4 a1 = *(const float4*)&As[kk][ty*8+4];
            float4 b0 = *(const float4*)&Bs[kk][tx*8];
            float4 b1 = *(const float4*)&Bs[kk][tx*8+4];
            float a[8] = {a0.x,a0.y,a0.z,a0.w,a1.x,a1.y,a1.z,a1.w};
            float b[8] = {b0.x,b0.y,b0.z,b0.w,b1.x,b1.y,b1.z,b1.w};
            #pragma unroll
            for (int i = 0; i < 8; i++)
                #pragma unroll
                for (int j = 0; j < 8; j++)
                    acc[i][j] += a[i] * b[j];
        }
    }

    float bb[8];
    #pragma unroll
    for (int j = 0; j < 8; j++) bb[j] = bp[bn + tx*8 + j];
    #pragma unroll
    for (int i = 0; i < 8; i++) {
        float* crow = out + (size_t)(bm + ty*8 + i) * Dc + bn + tx*8;
        *(float4*)(crow)     = make_float4(acc[i][0]+bb[0], acc[i][1]+bb[1],
                                           acc[i][2]+bb[2], acc[i][3]+bb[3]);
        *(float4*)(crow + 4) = make_float4(acc[i][4]+bb[4], acc[i][5]+bb[5],
                                           acc[i][6]+bb[6], acc[i][7]+bb[7]);
    }
}

// ---------------------------------------------------------------------------
extern "C" void kernel_launch(void* const* d_in, const int* in_sizes, int n_in,
                              void* d_out, int out_size)
{
    (void)in_sizes; (void)n_in; (void)out_size;
    const float* key   = (const float*)d_in[0];
    const float* query = (const float*)d_in[1];
    const float* value = (const float*)d_in[2];
    const unsigned int* mask = (const unsigned int*)d_in[3];
    const float* Wk = (const float*)d_in[4];
    const float* bk = (const float*)d_in[5];
    const float* Wq = (const float*)d_in[6];
    const float* bq = (const float*)d_in[7];
    const float* Wv = (const float*)d_in[8];
    const float* bv = (const float*)d_in[9];
    const float* Wp = (const float*)d_in[10];
    const float* bp = (const float*)d_in[11];

    float* att = (float*)d_out;                                  // [B*H, S, S]
    float* out = (float*)d_out + (size_t)Bc * Hc * Sc * Sc;      // [B, S, D]

    float *Qp, *Kp, *Vp, *Cx;
    cudaGetSymbolAddress((void**)&Qp, g_Q);
    cudaGetSymbolAddress((void**)&Kp, g_K);
    cudaGetSymbolAddress((void**)&Vp, g_V);
    cudaGetSymbolAddress((void**)&Cx, g_ctx);

    const float scale = 0.125f;   // 1/sqrt(64)

    dim3 gProj(Dc/128, Mrows/128);                 // (8, 64)
    proj_gemm<<<gProj, 256>>>(query, Wq, bq, Qp, Dc, Dc, scale);
    proj_gemm<<<gProj, 256>>>(key,   Wk, bk, Kp, Dc, Dc, 1.0f);
    proj_gemm<<<gProj, 256>>>(value, Wv, bv, Vp, Dc, Dc, 1.0f);

    scores_gemm<<<dim3(Sc/128, Sc/128, Bc*Hc), 256>>>(Qp, Kp, att);
    softmax_kernel<<<Bc*Hc*Sc, 256>>>(att, mask);
    ctx_gemm<<<dim3(1, Sc/128, Bc*Hc), 256>>>(att, Vp, Cx);
    out_gemm<<<dim3(Dc/128, Mrows/128), 256>>>(query, Cx, Wp, bp, out);
}

// round 2
// speedup vs baseline: 1.0021x; 1.0021x over previous
#include <cuda_runtime.h>
#include <cstdint>
#include <cstddef>

// Problem constants
#define Bc 8
#define Sc 1024
#define Dc 1024
#define Hc 16
#define DKc 64
#define Mrows (Bc*Sc)          // 8192

// Scratch (allocation-free rule: __device__ globals)
__device__ float g_Q[Bc*Sc*Dc];
__device__ float g_K[Bc*Sc*Dc];
__device__ float g_V[Bc*Sc*Dc];
__device__ float g_ctx[Bc*Sc*Dc];

// ---------------------------------------------------------------------------
// Projection GEMM: C[M,N] = alpha * (A[M,K] @ W[N,K]^T + bias[N])
// Tile 128x128, BK=8, 256 threads, 8x8 per-thread micro-tile.
// ---------------------------------------------------------------------------
__global__ __launch_bounds__(256) void proj_gemm(
    const float* __restrict__ A, const float* __restrict__ W,
    const float* __restrict__ bias, float* __restrict__ C,
    int Kdim, int Ndim, float alpha)
{
    __shared__ float As[8][128];
    __shared__ float Bs[8][128];
    const int bm = blockIdx.y * 128;
    const int bn = blockIdx.x * 128;
    const int tid = threadIdx.x;
    const int tx = tid & 15, ty = tid >> 4;

    float acc[8][8];
    #pragma unroll
    for (int i = 0; i < 8; i++)
        #pragma unroll
        for (int j = 0; j < 8; j++) acc[i][j] = 0.f;

    const int m_l = tid >> 1;        // 0..127
    const int kq  = tid & 1;         // 0..1  (two float4 per 8-wide k slab)
    const float* Arow = A + (size_t)(bm + m_l) * Kdim + kq * 4;
    const float* Wrow = W + (size_t)(bn + m_l) * Kdim + kq * 4;

    for (int k0 = 0; k0 < Kdim; k0 += 8) {
        float4 av = *(const float4*)(Arow + k0);
        float4 wv = *(const float4*)(Wrow + k0);
        __syncthreads();
        As[kq*4+0][m_l] = av.x; As[kq*4+1][m_l] = av.y;
        As[kq*4+2][m_l] = av.z; As[kq*4+3][m_l] = av.w;
        Bs[kq*4+0][m_l] = wv.x; Bs[kq*4+1][m_l] = wv.y;
        Bs[kq*4+2][m_l] = wv.z; Bs[kq*4+3][m_l] = wv.w;
        __syncthreads();
        #pragma unroll
        for (int kk = 0; kk < 8; kk++) {
            float4 a0 = *(const float4*)&As[kk][ty*8];
            float4 a1 = *(const float4*)&As[kk][ty*8+4];
            float4 b0 = *(const float4*)&Bs[kk][tx*8];
            float4 b1 = *(const float4*)&Bs[kk][tx*8+4];
            float a[8] = {a0.x,a0.y,a0.z,a0.w,a1.x,a1.y,a1.z,a1.w};
            float b[8] = {b0.x,b0.y,b0.z,b0.w,b1.x,b1.y,b1.z,b1.w};
            #pragma unroll
            for (int i = 0; i < 8; i++)
                #pragma unroll
                for (int j = 0; j < 8; j++)
                    acc[i][j] += a[i] * b[j];
        }
    }

    float bb[8];
    #pragma unroll
    for (int j = 0; j < 8; j++) bb[j] = bias[bn + tx*8 + j];
    #pragma unroll
    for (int i = 0; i < 8; i++) {
        float* crow = C + (size_t)(bm + ty*8 + i) * Ndim + bn + tx*8;
        float4 o0, o1;
        o0.x = alpha*(acc[i][0]+bb[0]); o0.y = alpha*(acc[i][1]+bb[1]);
        o0.z = alpha*(acc[i][2]+bb[2]); o0.w = alpha*(acc[i][3]+bb[3]);
        o1.x = alpha*(acc[i][4]+bb[4]); o1.y = alpha*(acc[i][5]+bb[5]);
        o1.z = alpha*(acc[i][6]+bb[6]); o1.w = alpha*(acc[i][7]+bb[7]);
        *(float4*)(crow)     = o0;
        *(float4*)(crow + 4) = o1;
    }
}

// ---------------------------------------------------------------------------
// Scores GEMM (per head): att[bh][q][k] = Qh[q,:] . Kh[k,:]  (scale folded in Q)
// Tile 128x128, K=64 (BK=8).
// ---------------------------------------------------------------------------
__global__ __launch_bounds__(256) void scores_gemm(
    const float* __restrict__ Q, const float* __restrict__ Km,
    float* __restrict__ att)
{
    const int bh = blockIdx.z;
    const int b  = bh >> 4;
    const int h  = bh & 15;
    const float* Aq = Q  + (size_t)b * Sc * Dc + h * DKc;   // row stride Dc
    const float* Bk = Km + (size_t)b * Sc * Dc + h * DKc;
    float* C = att + (size_t)bh * Sc * Sc;

    __shared__ float As[8][128];
    __shared__ float Bs[8][128];
    const int bm = blockIdx.y * 128;
    const int bn = blockIdx.x * 128;
    const int tid = threadIdx.x;
    const int tx = tid & 15, ty = tid >> 4;

    float acc[8][8];
    #pragma unroll
    for (int i = 0; i < 8; i++)
        #pragma unroll
        for (int j = 0; j < 8; j++) acc[i][j] = 0.f;

    const int m_l = tid >> 1;
    const int kq  = tid & 1;

    for (int k0 = 0; k0 < DKc; k0 += 8) {
        float4 av = *(const float4*)&Aq[(size_t)(bm + m_l) * Dc + k0 + kq*4];
        float4 bv = *(const float4*)&Bk[(size_t)(bn + m_l) * Dc + k0 + kq*4];
        __syncthreads();
        As[kq*4+0][m_l] = av.x; As[kq*4+1][m_l] = av.y;
        As[kq*4+2][m_l] = av.z; As[kq*4+3][m_l] = av.w;
        Bs[kq*4+0][m_l] = bv.x; Bs[kq*4+1][m_l] = bv.y;
        Bs[kq*4+2][m_l] = bv.z; Bs[kq*4+3][m_l] = bv.w;
        __syncthreads();
        #pragma unroll
        for (int kk = 0; kk < 8; kk++) {
            float4 a0 = *(const float4*)&As[kk][ty*8];
            float4 a1 = *(const float4*)&As[kk][ty*8+4];
            float4 b0 = *(const float4*)&Bs[kk][tx*8];
            float4 b1 = *(const float4*)&Bs[kk][tx*8+4];
            float a[8] = {a0.x,a0.y,a0.z,a0.w,a1.x,a1.y,a1.z,a1.w};
            float b[8] = {b0.x,b0.y,b0.z,b0.w,b1.x,b1.y,b1.z,b1.w};
            #pragma unroll
            for (int i = 0; i < 8; i++)
                #pragma unroll
                for (int j = 0; j < 8; j++)
                    acc[i][j] += a[i] * b[j];
        }
    }

    #pragma unroll
    for (int i = 0; i < 8; i++) {
        float* crow = C + (size_t)(bm + ty*8 + i) * Sc + bn + tx*8;
        *(float4*)(crow)     = make_float4(acc[i][0], acc[i][1], acc[i][2], acc[i][3]);
        *(float4*)(crow + 4) = make_float4(acc[i][4], acc[i][5], acc[i][6], acc[i][7]);
    }
}

// ---------------------------------------------------------------------------
// Softmax (in-place over att rows) with query-row masking.
// Masked rows -> exactly uniform 1/S (== softmax of constant -1e9 row).
// mask read as 4-byte nonzero test (covers float32 0/1 and int32 0/1).
// ---------------------------------------------------------------------------
__global__ __launch_bounds__(256) void softmax_kernel(
    float* __restrict__ att, const unsigned int* __restrict__ mask)
{
    const int row = blockIdx.x;           // bh*S + q
    const int q   = row & (Sc - 1);
    const int bh  = row >> 10;
    const int b   = bh >> 4;
    float* p = att + (size_t)row * Sc;
    const int tid = threadIdx.x;

    if (mask[b * Sc + q] != 0u) {
        const float u = 1.0f / (float)Sc;
        ((float4*)p)[tid] = make_float4(u, u, u, u);
        return;
    }

    __shared__ float sh[16];
    float4 x = ((const float4*)p)[tid];
    float mx = fmaxf(fmaxf(x.x, x.y), fmaxf(x.z, x.w));
    #pragma unroll
    for (int o = 16; o; o >>= 1) mx = fmaxf(mx, __shfl_xor_sync(0xffffffffu, mx, o));
    const int w = tid >> 5, l = tid & 31;
    if (l == 0) sh[w] = mx;
    __syncthreads();
    if (tid < 32) {
        float v = (l < 8) ? sh[l] : -3.4e38f;
        #pragma unroll
        for (int o = 4; o; o >>= 1) v = fmaxf(v, __shfl_xor_sync(0xffffffffu, v, o));
        if (l == 0) sh[8] = v;
    }
    __syncthreads();
    mx = sh[8];

    float e0 = __expf(x.x - mx), e1 = __expf(x.y - mx);
    float e2 = __expf(x.z - mx), e3 = __expf(x.w - mx);
    float s = e0 + e1 + e2 + e3;
    #pragma unroll
    for (int o = 16; o; o >>= 1) s += __shfl_xor_sync(0xffffffffu, s, o);
    if (l == 0) sh[w] = s;
    __syncthreads();
    if (tid < 32) {
        float v = (l < 8) ? sh[l] : 0.f;
        #pragma unroll
        for (int o = 4; o; o >>= 1) v += __shfl_xor_sync(0xffffffffu, v, o);
        if (l == 0) sh[9] = v;
    }
    __syncthreads();
    const float inv = 1.0f / sh[9];
    ((float4*)p)[tid] = make_float4(e0*inv, e1*inv, e2*inv, e3*inv);
}

// ---------------------------------------------------------------------------
// Context GEMM (per head): ctx[q, d] = sum_k att[q,k] * Vh[k,d]
// Tile 128(q) x 64(d), BK=16, 256 threads, 8x4 per-thread.
// ---------------------------------------------------------------------------
__global__ __launch_bounds__(256) void ctx_gemm(
    const float* __restrict__ att, const float* __restrict__ V,
    float* __restrict__ ctx)
{
    const int bh = blockIdx.z;
    const int b  = bh >> 4;
    const int h  = bh & 15;
    const float* A  = att + (size_t)bh * Sc * Sc;            // [S,S]
    const float* Vb = V   + (size_t)b * Sc * Dc + h * DKc;   // row stride Dc
    float* Cb       = ctx + (size_t)b * Sc * Dc + h * DKc;

    __shared__ float As[16][128];   // att chunk, k-major
    __shared__ float Bs[16][64];    // V chunk
    const int bm = blockIdx.y * 128;
    const int tid = threadIdx.x;
    const int tx = tid & 15, ty = tid >> 4;

    float acc[8][4];
    #pragma unroll
    for (int i = 0; i < 8; i++)
        #pragma unroll
        for (int j = 0; j < 4; j++) acc[i][j] = 0.f;

    for (int k0 = 0; k0 < Sc; k0 += 16) {
        // As: 128 m x 16 k = 512 float4-items (m=idx>>2, kq=idx&3), 2 per thread
        const int i0 = tid,       m0 = i0 >> 2, kq0 = i0 & 3;
        const int i1 = tid + 256, m1 = i1 >> 2, kq1 = i1 & 3;
        float4 a0v = *(const float4*)&A[(size_t)(bm + m0) * Sc + k0 + kq0*4];
        float4 a1v = *(const float4*)&A[(size_t)(bm + m1) * Sc + k0 + kq1*4];
        // Bs: 16 k x 64 n -> 256 float4-items: k=tid>>4, nq=tid&15
        const int kb = tid >> 4, nq = tid & 15;
        float4 bv = *(const float4*)&Vb[(size_t)(k0 + kb) * Dc + nq*4];
        __syncthreads();
        As[kq0*4+0][m0] = a0v.x; As[kq0*4+1][m0] = a0v.y;
        As[kq0*4+2][m0] = a0v.z; As[kq0*4+3][m0] = a0v.w;
        As[kq1*4+0][m1] = a1v.x; As[kq1*4+1][m1] = a1v.y;
        As[kq1*4+2][m1] = a1v.z; As[kq1*4+3][m1] = a1v.w;
        *(float4*)&Bs[kb][nq*4] = bv;
        __syncthreads();
        #pragma unroll
        for (int kk = 0; kk < 16; kk++) {
            float4 a0 = *(const float4*)&As[kk][ty*8];
            float4 a1 = *(const float4*)&As[kk][ty*8+4];
            float4 bq = *(const float4*)&Bs[kk][tx*4];
            float a[8] = {a0.x,a0.y,a0.z,a0.w,a1.x,a1.y,a1.z,a1.w};
            float bb[4] = {bq.x,bq.y,bq.z,bq.w};
            #pragma unroll
            for (int i = 0; i < 8; i++)
                #pragma unroll
                for (int j = 0; j < 4; j++)
                    acc[i][j] += a[i] * bb[j];
        }
    }

    #pragma unroll
    for (int i = 0; i < 8; i++) {
        *(float4*)&Cb[(size_t)(bm + ty*8 + i) * Dc + tx*4] =
            make_float4(acc[i][0], acc[i][1], acc[i][2], acc[i][3]);
    }
}

// ---------------------------------------------------------------------------
// Output GEMM: out[m,n] = sum_k concat(query,ctx)[m,k] * Wp[n,k] + bp[n]
// M=8192, N=1024, K=2048. Same 128x128x8 tiling.
// ---------------------------------------------------------------------------
__global__ __launch_bounds__(256) void out_gemm(
    const float* __restrict__ query, const float* __restrict__ ctx,
    const float* __restrict__ Wp, const float* __restrict__ bp,
    float* __restrict__ out)
{
    __shared__ float As[8][128];
    __shared__ float Bs[8][128];
    const int bm = blockIdx.y * 128;
    const int bn = blockIdx.x * 128;
    const int tid = threadIdx.x;
    const int tx = tid & 15, ty = tid >> 4;

    float acc[8][8];
    #pragma unroll
    for (int i = 0; i < 8; i++)
        #pragma unroll
        for (int j = 0; j < 8; j++) acc[i][j] = 0.f;

    const int m_l = tid >> 1;
    const int kq  = tid & 1;

    for (int k0 = 0; k0 < 2*Dc; k0 += 8) {
        const int kb = k0 + kq*4;
        const float* src = (kb < Dc)
            ? (query + (size_t)(bm + m_l) * Dc + kb)
            : (ctx   + (size_t)(bm + m_l) * Dc + (kb - Dc));
        float4 av = *(const float4*)src;
        float4 wv = *(const float4*)&Wp[(size_t)(bn + m_l) * (2*Dc) + kb];
        __syncthreads();
        As[kq*4+0][m_l] = av.x; As[kq*4+1][m_l] = av.y;
        As[kq*4+2][m_l] = av.z; As[kq*4+3][m_l] = av.w;
        Bs[kq*4+0][m_l] = wv.x; Bs[kq*4+1][m_l] = wv.y;
        Bs[kq*4+2][m_l] = wv.z; Bs[kq*4+3][m_l] = wv.w;
        __syncthreads();
        #pragma unroll
        for (int kk = 0; kk < 8; kk++) {
            float4 a0 = *(const float4*)&As[kk][ty*8];
            float4 a1 = *(const float4*)&As[kk][ty*8+4];
            float4 b0 = *(const float4*)&Bs[kk][tx*8];
            float4 b1 = *(const float4*)&Bs[kk][tx*8+4];
            float a[8] = {a0.x,a0.y,a0.z,a0.w,a1.x,a1.y,a1.z,a1.w};
            float b[8] = {b0.x,b0.y,b0.z,b0.w,b1.x,b1.y,b1.z,b1.w};
            #pragma unroll
            for (int i = 0; i < 8; i++)
                #pragma unroll
                for (int j = 0; j < 8; j++)
                    acc[i][j] += a[i] * b[j];
        }
    }

    float bb[8];
    #pragma unroll
    for (int j = 0; j < 8; j++) bb[j] = bp[bn + tx*8 + j];
    #pragma unroll
    for (int i = 0; i < 8; i++) {
        float* crow = out + (size_t)(bm + ty*8 + i) * Dc + bn + tx*8;
        *(float4*)(crow)     = make_float4(acc[i][0]+bb[0], acc[i][1]+bb[1],
                                           acc[i][2]+bb[2], acc[i][3]+bb[3]);
        *(float4*)(crow + 4) = make_float4(acc[i][4]+bb[4], acc[i][5]+bb[5],
                                           acc[i][6]+bb[6], acc[i][7]+bb[7]);
    }
}

// ---------------------------------------------------------------------------
extern "C" void kernel_launch(void* const* d_in, const int* in_sizes, int n_in,
                              void* d_out, int out_size)
{
    (void)in_sizes; (void)n_in; (void)out_size;
    const float* key   = (const float*)d_in[0];
    const float* query = (const float*)d_in[1];
    const float* value = (const float*)d_in[2];
    const unsigned int* mask = (const unsigned int*)d_in[3];
    const float* Wk = (const float*)d_in[4];
    const float* bk = (const float*)d_in[5];
    const float* Wq = (const float*)d_in[6];
    const float* bq = (const float*)d_in[7];
    const float* Wv = (const float*)d_in[8];
    const float* bv = (const float*)d_in[9];
    const float* Wp = (const float*)d_in[10];
    const float* bp = (const float*)d_in[11];

    float* att = (float*)d_out;                                  // [B*H, S, S]
    float* out = (float*)d_out + (size_t)Bc * Hc * Sc * Sc;      // [B, S, D]

    float *Qp, *Kp, *Vp, *Cx;
    cudaGetSymbolAddress((void**)&Qp, g_Q);
    cudaGetSymbolAddress((void**)&Kp, g_K);
    cudaGetSymbolAddress((void**)&Vp, g_V);
    cudaGetSymbolAddress((void**)&Cx, g_ctx);

    const float scale = 0.125f;   // 1/sqrt(64)

    dim3 gProj(Dc/128, Mrows/128);                 // (8, 64)
    proj_gemm<<<gProj, 256>>>(query, Wq, bq, Qp, Dc, Dc, scale);
    proj_gemm<<<gProj, 256>>>(key,   Wk, bk, Kp, Dc, Dc, 1.0f);
    proj_gemm<<<gProj, 256>>>(value, Wv, bv, Vp, Dc, Dc, 1.0f);

    scores_gemm<<<dim3(Sc/128, Sc/128, Bc*Hc), 256>>>(Qp, Kp, att);
    softmax_kernel<<<Bc*Hc*Sc, 256>>>(att, mask);
    ctx_gemm<<<dim3(1, Sc/128, Bc*Hc), 256>>>(att, Vp, Cx);
    out_gemm<<<dim3(Dc/128, Mrows/128), 256>>>(query, Cx, Wp, bp, out);
}

// round 4
// speedup vs baseline: 1.4103x; 1.4073x over previous
#include <cuda_runtime.h>
#include <cuda_fp16.h>
#include <cstdint>
#include <cstddef>

#define Bc 8
#define Sc 1024
#define Dc 1024
#define Hc 16
#define DKc 64
#define Mrows (Bc*Sc)
#define BHc (Bc*Hc)

typedef long long ll;

// ---------------- scratch ----------------
__device__ __half g_q_in[(size_t)Mrows*3*Dc];     // [8192,3072] A-pattern [hi|hi|lo]
__device__ __half g_k_in[(size_t)Mrows*3*Dc];
__device__ __half g_v_in[(size_t)Mrows*3*Dc];
__device__ __half g_Wqs[(size_t)Dc*3*Dc];         // B-pattern [hi|lo|hi]
__device__ __half g_Wks[(size_t)Dc*3*Dc];
__device__ __half g_Wvs[(size_t)Dc*3*Dc];
__device__ __half g_Wps[(size_t)Dc*6*Dc];
__device__ float g_Qf[(size_t)Mrows*Dc];
__device__ float g_Kf[(size_t)Mrows*Dc];
__device__ float g_Vf[(size_t)Mrows*Dc];
__device__ float g_ctxf[(size_t)Mrows*Dc];
__device__ __half g_qh[(size_t)BHc*Sc*3*DKc];     // [128][1024][192] A-pattern
__device__ __half g_kh[(size_t)BHc*Sc*3*DKc];     // B-pattern
__device__ __half g_vh[(size_t)BHc*DKc*2*Sc];     // [128][64][hi 1024 | lo 1024]
__device__ __half g_ctxs[(size_t)Mrows*3*Dc];     // ctx A-pattern

__device__ __forceinline__ uint32_t smem_u32(const void* p){
    uint32_t r;
    asm("{ .reg .u64 t; cvta.to.shared.u64 t, %1; cvt.u32.u64 %0, t; }" : "=r"(r) : "l"(p));
    return r;
}
#define SWZ(o) ((o) ^ (((o) >> 3) & 0x70))

#define LDSM4(r0,r1,r2,r3,addr) \
    asm volatile("ldmatrix.sync.aligned.m8n8.x4.shared.b16 {%0,%1,%2,%3}, [%4];" \
        : "=r"(r0), "=r"(r1), "=r"(r2), "=r"(r3) : "r"(addr))

#define MMA4(d,a,b0,b1) \
    asm volatile("mma.sync.aligned.m16n8k16.row.col.f32.f16.f16.f32 " \
        "{%0,%1,%2,%3},{%4,%5,%6,%7},{%8,%9},{%0,%1,%2,%3};" \
        : "+f"((d)[0]), "+f"((d)[1]), "+f"((d)[2]), "+f"((d)[3]) \
        : "r"((a)[0]), "r"((a)[1]), "r"((a)[2]), "r"((a)[3]), "r"(b0), "r"(b1))

__device__ __forceinline__ uint32_t pack2h(float a, float b){
    __half2 t = __floats2half2_rn(a, b);
    return *reinterpret_cast<uint32_t*>(&t);
}

// ============================================================================
// Generic fp16 HMMA GEMM: C[128x128 tiles] = A'@B'^T (+bias), two K-segments.
// 256 thr = 8 warps (4m x 2n), warp tile 32x64, BK=64, double-buffered smem.
// ============================================================================
__global__ __launch_bounds__(256) void gemm_hmma(
    const __half* __restrict__ A0, ll ldA0, ll zA0,
    const __half* __restrict__ B0, ll ldB0, int nc0,
    const __half* __restrict__ A1, ll ldA1,
    const __half* __restrict__ B1, ll ldB1, int nc1,
    float* __restrict__ C, ll ldC, ll zC,
    const float* __restrict__ bias)
{
    extern __shared__ char sm[];   // A bufs [2][16KB] @0, B bufs [2][16KB] @32KB
    const int tid = threadIdx.x, lane = tid & 31, wid = tid >> 5;
    const int wm = wid >> 1, wn = wid & 1;
    const int z = blockIdx.z;
    const ll bm = (ll)blockIdx.y * 128, bn = (ll)blockIdx.x * 128;
    A0 += (ll)z * zA0; B0 += (ll)z * zA0; C += (ll)z * zC;
    const uint32_t sbase = smem_u32(sm);

    float acc[2][8][4];
    #pragma unroll
    for (int i = 0; i < 2; i++)
        #pragma unroll
        for (int j = 0; j < 8; j++)
            #pragma unroll
            for (int k = 0; k < 4; k++) acc[i][j][k] = 0.f;

    const int NC = nc0 + nc1;
    const int row = tid >> 1, hf = tid & 1;

    // ldmatrix address components
    const int arow = wm * 32 + (lane & 7) + ((lane >> 3) & 1) * 8;
    const int acol8 = ((lane >> 4) & 1) * 8;
    const int brow = wn * 64 + (lane & 7) + ((lane >> 4) & 1) * 8;
    const int bcol8 = ((lane >> 3) & 1) * 8;

    // prologue: chunk 0 -> buf 0
    {
        const __half* Ap = (0 < nc0) ? A0 : A1;  ll lda = (0 < nc0) ? ldA0 : ldA1;
        const __half* Bp = (0 < nc0) ? B0 : B1;  ll ldb = (0 < nc0) ? ldB0 : ldB1;
        const char* ag = (const char*)(Ap + (bm + row) * lda) + hf * 64;
        const char* bg = (const char*)(Bp + (bn + row) * ldb) + hf * 64;
        #pragma unroll
        for (int j = 0; j < 4; j++){
            float4 av = *(const float4*)(ag + j * 16);
            float4 bv = *(const float4*)(bg + j * 16);
            uint32_t sw = SWZ((uint32_t)row * 128u + hf * 64u + j * 16u);
            *(float4*)(sm + sw) = av;
            *(float4*)(sm + 32768 + sw) = bv;
        }
    }
    __syncthreads();

    for (int c = 0; c < NC; c++){
        const int buf = c & 1;
        float4 av[4], bv[4];
        const bool pre = (c + 1 < NC);
        if (pre){
            int cn = c + 1;
            const __half *Ap, *Bp; ll lda, ldb; int cc;
            if (cn < nc0){ Ap = A0; lda = ldA0; Bp = B0; ldb = ldB0; cc = cn; }
            else         { Ap = A1; lda = ldA1; Bp = B1; ldb = ldB1; cc = cn - nc0; }
            const char* ag = (const char*)(Ap + (bm + row) * lda + (ll)cc * 64) + hf * 64;
            const char* bg = (const char*)(Bp + (bn + row) * ldb + (ll)cc * 64) + hf * 64;
            #pragma unroll
            for (int j = 0; j < 4; j++){
                av[j] = *(const float4*)(ag + j * 16);
                bv[j] = *(const float4*)(bg + j * 16);
            }
        }
        // compute on buf
        {
            const uint32_t ab = sbase + buf * 16384u;
            const uint32_t bb = sbase + 32768u + buf * 16384u;
            #pragma unroll
            for (int ks = 0; ks < 4; ks++){
                uint32_t a[2][4];
                #pragma unroll
                for (int mt = 0; mt < 2; mt++){
                    uint32_t ad = ab + SWZ((uint32_t)(arow + mt * 16) * 128u + (ks * 16 + acol8) * 2u);
                    LDSM4(a[mt][0], a[mt][1], a[mt][2], a[mt][3], ad);
                }
                #pragma unroll
                for (int np = 0; np < 4; np++){
                    uint32_t b0, b1, b2, b3;
                    uint32_t bd = bb + SWZ((uint32_t)(brow + np * 16) * 128u + (ks * 16 + bcol8) * 2u);
                    LDSM4(b0, b1, b2, b3, bd);
                    #pragma unroll
                    for (int mt = 0; mt < 2; mt++){
                        MMA4(acc[mt][np * 2],     a[mt], b0, b1);
                        MMA4(acc[mt][np * 2 + 1], a[mt], b2, b3);
                    }
                }
            }
        }
        if (pre){
            char* ab = sm + (buf ^ 1) * 16384;
            char* bb = sm + 32768 + (buf ^ 1) * 16384;
            #pragma unroll
            for (int j = 0; j < 4; j++){
                uint32_t sw = SWZ((uint32_t)row * 128u + hf * 64u + j * 16u);
                *(float4*)(ab + sw) = av[j];
                *(float4*)(bb + sw) = bv[j];
            }
        }
        __syncthreads();
    }

    // epilogue
    #pragma unroll
    for (int mt = 0; mt < 2; mt++){
        #pragma unroll
        for (int nt = 0; nt < 8; nt++){
            ll r0 = bm + wm * 32 + mt * 16 + (lane >> 2);
            ll col = bn + wn * 64 + nt * 8 + (lane & 3) * 2;
            float bx = 0.f, by = 0.f;
            if (bias){ bx = bias[col]; by = bias[col + 1]; }
            float2 v0 = make_float2(acc[mt][nt][0] + bx, acc[mt][nt][1] + by);
            float2 v1 = make_float2(acc[mt][nt][2] + bx, acc[mt][nt][3] + by);
            *(float2*)&C[r0 * ldC + col] = v0;
            *(float2*)&C[(r0 + 8) * ldC + col] = v1;
        }
    }
}

// ============================================================================
// ctx GEMM: ctx[q,dk] = sum_k att[q,k]*V[k,dk]; att fp32 split on the fly.
// Block tile 128(q) x 64(dk); warp 32x32; single-buffered (hi/lo x A/B).
// ============================================================================
__global__ __launch_bounds__(256) void ctx_hmma(
    const float* __restrict__ att, const __half* __restrict__ vh,
    float* __restrict__ ctxf)
{
    extern __shared__ char sm[];   // Ahi@0 16KB, Alo@16K, Bhi@32K 8KB, Blo@40K 8KB
    const int tid = threadIdx.x, lane = tid & 31, wid = tid >> 5;
    const int wm = wid >> 1, wn = wid & 1;
    const int z = blockIdx.z;
    const ll bm = (ll)blockIdx.y * 128;
    const uint32_t sbase = smem_u32(sm);

    float acc[2][4][4];
    #pragma unroll
    for (int i = 0; i < 2; i++)
        #pragma unroll
        for (int j = 0; j < 4; j++)
            #pragma unroll
            for (int k = 0; k < 4; k++) acc[i][j][k] = 0.f;

    const int row = tid >> 1, hf = tid & 1;
    const float* ap = att + ((ll)z * Sc + bm + row) * Sc + hf * 32;
    const int vsel = tid >> 7, vr = (tid >> 1) & 63, vhf = tid & 1;
    const __half* vp = vh + ((ll)z * 64 + vr) * 2048 + vsel * 1024 + vhf * 32;

    const int arow = wm * 32 + (lane & 7) + ((lane >> 3) & 1) * 8;
    const int acol8 = ((lane >> 4) & 1) * 8;
    const int brow = wn * 32 + (lane & 7) + ((lane >> 4) & 1) * 8;
    const int bcol8 = ((lane >> 3) & 1) * 8;

    for (int c = 0; c < 16; c++){
        __syncthreads();
        // att -> hi/lo fp16 split into smem
        #pragma unroll
        for (int j = 0; j < 4; j++){
            float4 x0 = *(const float4*)(ap + c * 64 + j * 8);
            float4 x1 = *(const float4*)(ap + c * 64 + j * 8 + 4);
            float f[8] = {x0.x, x0.y, x0.z, x0.w, x1.x, x1.y, x1.z, x1.w};
            float h[8], l[8];
            #pragma unroll
            for (int e = 0; e < 8; e++){
                __half hh = __float2half_rn(f[e]);
                h[e] = __half2float(hh);
                l[e] = f[e] - h[e];
            }
            uint4 Hv, Lv;
            Hv.x = pack2h(h[0], h[1]); Hv.y = pack2h(h[2], h[3]);
            Hv.z = pack2h(h[4], h[5]); Hv.w = pack2h(h[6], h[7]);
            Lv.x = pack2h(l[0], l[1]); Lv.y = pack2h(l[2], l[3]);
            Lv.z = pack2h(l[4], l[5]); Lv.w = pack2h(l[6], l[7]);
            uint32_t sw = SWZ((uint32_t)row * 128u + hf * 64u + j * 16u);
            *(uint4*)(sm + sw) = Hv;
            *(uint4*)(sm + 16384 + sw) = Lv;
        }
        // V hi/lo (already fp16) into smem
        {
            char* dst = sm + 32768 + vsel * 8192;
            #pragma unroll
            for (int j = 0; j < 4; j++){
                float4 v = *(const float4*)(vp + c * 64 + j * 8);
                uint32_t sw = SWZ((uint32_t)vr * 128u + vhf * 64u + j * 16u);
                *(float4*)(dst + sw) = v;
            }
        }
        __syncthreads();

        const uint32_t ah = sbase, al = sbase + 16384u;
        const uint32_t bh = sbase + 32768u, bl = sbase + 40960u;
        #pragma unroll
        for (int ks = 0; ks < 4; ks++){
            uint32_t Ah[2][4], Al[2][4];
            #pragma unroll
            for (int mt = 0; mt < 2; mt++){
                uint32_t off = SWZ((uint32_t)(arow + mt * 16) * 128u + (ks * 16 + acol8) * 2u);
                LDSM4(Ah[mt][0], Ah[mt][1], Ah[mt][2], Ah[mt][3], ah + off);
                LDSM4(Al[mt][0], Al[mt][1], Al[mt][2], Al[mt][3], al + off);
            }
            #pragma unroll
            for (int np = 0; np < 2; np++){
                uint32_t off = SWZ((uint32_t)(brow + np * 16) * 128u + (ks * 16 + bcol8) * 2u);
                uint32_t h0, h1, h2, h3, l0, l1, l2, l3;
                LDSM4(h0, h1, h2, h3, bh + off);
                LDSM4(l0, l1, l2, l3, bl + off);
                #pragma unroll
                for (int mt = 0; mt < 2; mt++){
                    MMA4(acc[mt][np * 2],     Ah[mt], h0, h1);
                    MMA4(acc[mt][np * 2 + 1], Ah[mt], h2, h3);
                    MMA4(acc[mt][np * 2],     Ah[mt], l0, l1);
                    MMA4(acc[mt][np * 2 + 1], Ah[mt], l2, l3);
                    MMA4(acc[mt][np * 2],     Al[mt], h0, h1);
                    MMA4(acc[mt][np * 2 + 1], Al[mt], h2, h3);
                }
            }
        }
    }

    const int b = z >> 4, h = z & 15;
    #pragma unroll
    for (int mt = 0; mt < 2; mt++){
        #pragma unroll
        for (int nt = 0; nt < 4; nt++){
            ll r = bm + wm * 32 + mt * 16 + (lane >> 2);
            ll col = (ll)h * 64 + wn * 32 + nt * 8 + (lane & 3) * 2;
            *(float2*)&ctxf[((ll)b * Sc + r) * Dc + col] =
                make_float2(acc[mt][nt][0], acc[mt][nt][1]);
            *(float2*)&ctxf[((ll)b * Sc + r + 8) * Dc + col] =
                make_float2(acc[mt][nt][2], acc[mt][nt][3]);
        }
    }
}

// ============================================================================
// Conversions (fp16 split)
// ============================================================================
__global__ void splitA_dup(const float* __restrict__ X, __half* __restrict__ O, int Cdim)
{
    ll e = ((ll)blockIdx.x * blockDim.x + threadIdx.x) * 2;
    ll r = e / Cdim; int c = (int)(e % Cdim);
    float2 v = *(const float2*)(X + e);
    __half hx = __float2half_rn(v.x), hy = __float2half_rn(v.y);
    uint32_t H; { __half2 t = __halves2half2(hx, hy); H = *(uint32_t*)&t; }
    uint32_t L = pack2h(v.x - __half2float(hx), v.y - __half2float(hy));
    __half* o = O + r * (ll)(3 * Cdim) + c;
    *(uint32_t*)(o) = H; *(uint32_t*)(o + Cdim) = H; *(uint32_t*)(o + 2 * Cdim) = L;
}
__global__ void splitB(const float* __restrict__ X, ll ldin,
                       __half* __restrict__ O, ll ldout, int Cdim)
{
    ll e = ((ll)blockIdx.x * blockDim.x + threadIdx.x) * 2;
    ll r = e / Cdim; int c = (int)(e % Cdim);
    float2 v = *(const float2*)(X + r * ldin + c);
    __half hx = __float2half_rn(v.x), hy = __float2half_rn(v.y);
    uint32_t H; { __half2 t = __halves2half2(hx, hy); H = *(uint32_t*)&t; }
    uint32_t L = pack2h(v.x - __half2float(hx), v.y - __half2float(hy));
    __half* o = O + r * ldout + c;
    *(uint32_t*)(o) = H; *(uint32_t*)(o + Cdim) = L; *(uint32_t*)(o + 2 * Cdim) = H;
}
__global__ void head_split(const float* __restrict__ X, __half* __restrict__ O,
                           int offDup, int offLo, float scale)
{
    ll e = ((ll)blockIdx.x * blockDim.x + threadIdx.x) * 2;
    ll tok = e >> 10; int d = (int)(e & 1023);
    int h = d >> 6, dk = d & 63;
    ll b = tok >> 10, s = tok & 1023;
    float2 v = *(const float2*)(X + e);
    v.x *= scale; v.y *= scale;
    __half hx = __float2half_rn(v.x), hy = __float2half_rn(v.y);
    uint32_t H; { __half2 t = __halves2half2(hx, hy); H = *(uint32_t*)&t; }
    uint32_t L = pack2h(v.x - __half2float(hx), v.y - __half2float(hy));
    __half* o = O + (((ll)(b * 16 + h) * 1024 + s) * 192) + dk;
    *(uint32_t*)(o) = H; *(uint32_t*)(o + offDup) = H; *(uint32_t*)(o + offLo) = L;
}
__global__ void vT_split(const float* __restrict__ X, __half* __restrict__ O)
{
    ll e = (ll)blockIdx.x * blockDim.x + threadIdx.x;
    int kk = (int)(e & 1023); ll t = e >> 10;
    int dk = (int)(t & 63);   ll t2 = t >> 6;
    int h = (int)(t2 & 15);   int b = (int)(t2 >> 4);
    float x = X[((ll)b * 1024 + kk) * 1024 + h * 64 + dk];
    __half hx = __float2half_rn(x);
    ll o = (((ll)(b * 16 + h) * 64 + dk) * 2048) + kk;
    O[o] = hx;
    O[o + 1024] = __float2half_rn(x - __half2float(hx));
}

// ===== softmax (known-correct) =====
__global__ void __launch_bounds__(256) softmax_kernel(
    float* __restrict__ att, const unsigned int* __restrict__ mask)
{
    const int row = blockIdx.x;
    const int q = row & (Sc - 1);
    const int bh = row >> 10, b = bh >> 4;
    float* p = att + (size_t)row * Sc;
    const int tid = threadIdx.x;
    if (mask[b * Sc + q] != 0u){
        const float u = 1.0f / (float)Sc;
        ((float4*)p)[tid] = make_float4(u, u, u, u);
        return;
    }
    __shared__ float sh[16];
    float4 x = ((const float4*)p)[tid];
    float mx = fmaxf(fmaxf(x.x, x.y), fmaxf(x.z, x.w));
    #pragma unroll
    for (int o = 16; o; o >>= 1) mx = fmaxf(mx, __shfl_xor_sync(0xffffffffu, mx, o));
    const int w = tid >> 5, l = tid & 31;
    if (l == 0) sh[w] = mx;
    __syncthreads();
    if (tid < 32){
        float v = (l < 8) ? sh[l] : -3.4e38f;
        #pragma unroll
        for (int o = 4; o; o >>= 1) v = fmaxf(v, __shfl_xor_sync(0xffffffffu, v, o));
        if (l == 0) sh[8] = v;
    }
    __syncthreads();
    mx = sh[8];
    float e0 = __expf(x.x - mx), e1 = __expf(x.y - mx);
    float e2 = __expf(x.z - mx), e3 = __expf(x.w - mx);
    float s = e0 + e1 + e2 + e3;
    #pragma unroll
    for (int o = 16; o; o >>= 1) s += __shfl_xor_sync(0xffffffffu, s, o);
    if (l == 0) sh[w] = s;
    __syncthreads();
    if (tid < 32){
        float v = (l < 8) ? sh[l] : 0.f;
        #pragma unroll
        for (int o = 4; o; o >>= 1) v += __shfl_xor_sync(0xffffffffu, v, o);
        if (l == 0) sh[9] = v;
    }
    __syncthreads();
    const float inv = 1.0f / sh[9];
    ((float4*)p)[tid] = make_float4(e0 * inv, e1 * inv, e2 * inv, e3 * inv);
}

extern "C" void kernel_launch(void* const* d_in, const int* in_sizes, int n_in,
                              void* d_out, int out_size)
{
    (void)in_sizes; (void)n_in; (void)out_size;
    const float* key   = (const float*)d_in[0];
    const float* query = (const float*)d_in[1];
    const float* value = (const float*)d_in[2];
    const unsigned int* mask = (const unsigned int*)d_in[3];
    const float* Wk = (const float*)d_in[4];
    const float* bk = (const float*)d_in[5];
    const float* Wq = (const float*)d_in[6];
    const float* bq = (const float*)d_in[7];
    const float* Wv = (const float*)d_in[8];
    const float* bv = (const float*)d_in[9];
    const float* Wp = (const float*)d_in[10];
    const float* bp = (const float*)d_in[11];

    float* att = (float*)d_out;
    float* outp = (float*)d_out + (size_t)BHc * Sc * Sc;

    __half *q_in,*k_in,*v_in,*wq,*wk,*wv,*wp,*qh,*kh,*vhp,*ctxs;
    float *Qf,*Kf,*Vf,*ctxf;
    cudaGetSymbolAddress((void**)&q_in, g_q_in);
    cudaGetSymbolAddress((void**)&k_in, g_k_in);
    cudaGetSymbolAddress((void**)&v_in, g_v_in);
    cudaGetSymbolAddress((void**)&wq, g_Wqs);
    cudaGetSymbolAddress((void**)&wk, g_Wks);
    cudaGetSymbolAddress((void**)&wv, g_Wvs);
    cudaGetSymbolAddress((void**)&wp, g_Wps);
    cudaGetSymbolAddress((void**)&qh, g_qh);
    cudaGetSymbolAddress((void**)&kh, g_kh);
    cudaGetSymbolAddress((void**)&vhp, g_vh);
    cudaGetSymbolAddress((void**)&ctxs, g_ctxs);
    cudaGetSymbolAddress((void**)&Qf, g_Qf);
    cudaGetSymbolAddress((void**)&Kf, g_Kf);
    cudaGetSymbolAddress((void**)&Vf, g_Vf);
    cudaGetSymbolAddress((void**)&ctxf, g_ctxf);

    cudaFuncSetAttribute(gemm_hmma, cudaFuncAttributeMaxDynamicSharedMemorySize, 65536);
    cudaFuncSetAttribute(ctx_hmma, cudaFuncAttributeMaxDynamicSharedMemorySize, 49152);
    const int GS = 65536, CS = 49152;

    // splits
    splitA_dup<<<(Mrows*Dc/2)/256, 256>>>(query, q_in, Dc);
    splitA_dup<<<(Mrows*Dc/2)/256, 256>>>(key,   k_in, Dc);
    splitA_dup<<<(Mrows*Dc/2)/256, 256>>>(value, v_in, Dc);
    splitB<<<(Dc*Dc/2)/256, 256>>>(Wq, Dc, wq, 3*Dc, Dc);
    splitB<<<(Dc*Dc/2)/256, 256>>>(Wk, Dc, wk, 3*Dc, Dc);
    splitB<<<(Dc*Dc/2)/256, 256>>>(Wv, Dc, wv, 3*Dc, Dc);
    splitB<<<(Dc*Dc/2)/256, 256>>>(Wp,      2*Dc, wp,        6*Dc, Dc);
    splitB<<<(Dc*Dc/2)/256, 256>>>(Wp + Dc, 2*Dc, wp + 3*Dc, 6*Dc, Dc);

    // projections
    dim3 gP(Dc/128, Mrows/128, 1);
    gemm_hmma<<<gP, 256, GS>>>(q_in, 3*Dc, 0, wq, 3*Dc, 48, q_in, 3*Dc, wq, 3*Dc, 0, Qf, Dc, 0, bq);
    gemm_hmma<<<gP, 256, GS>>>(k_in, 3*Dc, 0, wk, 3*Dc, 48, k_in, 3*Dc, wk, 3*Dc, 0, Kf, Dc, 0, bk);
    gemm_hmma<<<gP, 256, GS>>>(v_in, 3*Dc, 0, wv, 3*Dc, 48, v_in, 3*Dc, wv, 3*Dc, 0, Vf, Dc, 0, bv);

    // per-head splits
    head_split<<<(Mrows*Dc/2)/256, 256>>>(Qf, qh, 64, 128, 0.125f);   // A pattern
    head_split<<<(Mrows*Dc/2)/256, 256>>>(Kf, kh, 128, 64, 1.0f);     // B pattern
    vT_split<<<(int)(((ll)BHc*DKc*Sc)/256), 256>>>(Vf, vhp);

    // scores
    gemm_hmma<<<dim3(Sc/128, Sc/128, BHc), 256, GS>>>(
        qh, 192, (ll)Sc*192, kh, 192, 3, qh, 192, kh, 192, 0, att, Sc, (ll)Sc*Sc, nullptr);

    softmax_kernel<<<BHc*Sc, 256>>>(att, mask);

    ctx_hmma<<<dim3(1, Sc/128, BHc), 256, CS>>>(att, vhp, ctxf);

    splitA_dup<<<(Mrows*Dc/2)/256, 256>>>(ctxf, ctxs, Dc);

    // output projection
    gemm_hmma<<<gP, 256, GS>>>(q_in, 3*Dc, 0, wp, 6*Dc, 48,
                               ctxs, 3*Dc, wp + 3*Dc, 6*Dc, 48, outp, Dc, 0, bp);
}

// round 5
// speedup vs baseline: 1.9270x; 1.3665x over previous
#include <cuda_runtime.h>
#include <cuda_fp16.h>
#include <cstdint>
#include <cstddef>

#define Bc 8
#define Sc 1024
#define Dc 1024
#define Hc 16
#define DKc 64
#define Mrows (Bc*Sc)
#define BHc (Bc*Hc)

typedef long long ll;

// ---------------- scratch ----------------
// combined QKV input splits (A-pattern [hi|hi|lo]) and weights (B-pattern [hi|lo|hi])
__device__ __half g_in3[(size_t)3*Mrows*3*Dc];    // z: 0=query 1=key 2=value
__device__ __half g_W3[(size_t)3*Dc*3*Dc];        // z: 0=Wq 1=Wk 2=Wv
__device__ __half g_Wps[(size_t)Dc*6*Dc];
__device__ float g_F3[(size_t)3*Mrows*Dc];        // z: 0=Qf 1=Kf 2=Vf
__device__ float g_ctxf[(size_t)Mrows*Dc];
__device__ __half g_qh[(size_t)BHc*Sc*3*DKc];     // [128][1024][192] A-pattern
__device__ __half g_kh[(size_t)BHc*Sc*3*DKc];     // B-pattern
__device__ __half g_vh[(size_t)BHc*DKc*2*Sc];     // [128][64][hi 1024 | lo 1024]
__device__ __half g_ctxs[(size_t)Mrows*3*Dc];     // ctx A-pattern

__device__ __forceinline__ uint32_t smem_u32(const void* p){
    uint32_t r;
    asm("{ .reg .u64 t; cvta.to.shared.u64 t, %1; cvt.u32.u64 %0, t; }" : "=r"(r) : "l"(p));
    return r;
}
#define SWZ(o) ((o) ^ (((o) >> 3) & 0x70))

#define LDSM4(r0,r1,r2,r3,addr) \
    asm volatile("ldmatrix.sync.aligned.m8n8.x4.shared.b16 {%0,%1,%2,%3}, [%4];" \
        : "=r"(r0), "=r"(r1), "=r"(r2), "=r"(r3) : "r"(addr))

#define MMA4(d,a,b0,b1) \
    asm volatile("mma.sync.aligned.m16n8k16.row.col.f32.f16.f16.f32 " \
        "{%0,%1,%2,%3},{%4,%5,%6,%7},{%8,%9},{%0,%1,%2,%3};" \
        : "+f"((d)[0]), "+f"((d)[1]), "+f"((d)[2]), "+f"((d)[3]) \
        : "r"((a)[0]), "r"((a)[1]), "r"((a)[2]), "r"((a)[3]), "r"(b0), "r"(b1))

#define CPA16(saddr, gptr) \
    asm volatile("cp.async.cg.shared.global [%0], [%1], 16;" :: "r"(saddr), "l"(gptr))
#define CPA_COMMIT() asm volatile("cp.async.commit_group;" ::: "memory")

__device__ __forceinline__ uint32_t pack2h(float a, float b){
    __half2 t = __floats2half2_rn(a, b);
    return *reinterpret_cast<uint32_t*>(&t);
}

// ============================================================================
// Generic fp16 HMMA GEMM, cp.async 3-stage pipeline.
// C[128x128 tiles] = A'@B'^T (+bias). 8 warps (4m x 2n), warp 32x64, BK=64.
// smem: A stages [3][16KB] @0, B stages [3][16KB] @48KB  (96KB total)
// ============================================================================
__global__ __launch_bounds__(256, 2) void gemm_hmma(
    const __half* __restrict__ A0, ll ldA0, ll zA0,
    const __half* __restrict__ B0, ll ldB0, ll zB0, int nc0,
    const __half* __restrict__ A1, ll ldA1,
    const __half* __restrict__ B1, ll ldB1, int nc1,
    float* __restrict__ C, ll ldC, ll zC,
    const float* __restrict__ bias0, const float* __restrict__ bias1,
    const float* __restrict__ bias2)
{
    extern __shared__ char sm[];
    const int tid = threadIdx.x, lane = tid & 31, wid = tid >> 5;
    const int wm = wid >> 1, wn = wid & 1;
    const int z = blockIdx.z;
    const ll bm = (ll)blockIdx.y * 128, bn = (ll)blockIdx.x * 128;
    A0 += (ll)z * zA0; B0 += (ll)z * zB0; C += (ll)z * zC;
    const float* bias = (z == 0) ? bias0 : (z == 1) ? bias1 : bias2;
    const uint32_t sbase = smem_u32(sm);

    float acc[2][8][4];
    #pragma unroll
    for (int i = 0; i < 2; i++)
        #pragma unroll
        for (int j = 0; j < 8; j++)
            #pragma unroll
            for (int k = 0; k < 4; k++) acc[i][j][k] = 0.f;

    const int NC = nc0 + nc1;
    const int row = tid >> 1, hf = tid & 1;

    auto issue = [&](int c){
        const int s = c % 3;
        const __half *Ap, *Bp; ll lda, ldb; int cc;
        if (c < nc0){ Ap = A0; lda = ldA0; Bp = B0; ldb = ldB0; cc = c; }
        else        { Ap = A1; lda = ldA1; Bp = B1; ldb = ldB1; cc = c - nc0; }
        const char* ag = (const char*)(Ap + (bm + row) * lda + (ll)cc * 64) + hf * 64;
        const char* bg = (const char*)(Bp + (bn + row) * ldb + (ll)cc * 64) + hf * 64;
        const uint32_t as = sbase + (uint32_t)s * 16384u;
        const uint32_t bs = sbase + 49152u + (uint32_t)s * 16384u;
        #pragma unroll
        for (int j = 0; j < 4; j++){
            uint32_t sw = SWZ((uint32_t)row * 128u + hf * 64u + j * 16u);
            CPA16(as + sw, ag + j * 16);
            CPA16(bs + sw, bg + j * 16);
        }
        CPA_COMMIT();
    };

    // ldmatrix address components
    const int arow = wm * 32 + (lane & 7) + ((lane >> 3) & 1) * 8;
    const int acol8 = ((lane >> 4) & 1) * 8;
    const int brow = wn * 64 + (lane & 7) + ((lane >> 4) & 1) * 8;
    const int bcol8 = ((lane >> 3) & 1) * 8;

    issue(0);
    if (NC > 1) issue(1);

    for (int c = 0; c < NC; c++){
        if (c + 1 < NC) asm volatile("cp.async.wait_group 1;" ::: "memory");
        else            asm volatile("cp.async.wait_group 0;" ::: "memory");
        __syncthreads();
        if (c + 2 < NC) issue(c + 2);

        const int buf = c % 3;
        const uint32_t ab = sbase + (uint32_t)buf * 16384u;
        const uint32_t bb = sbase + 49152u + (uint32_t)buf * 16384u;
        #pragma unroll
        for (int ks = 0; ks < 4; ks++){
            uint32_t a[2][4];
            #pragma unroll
            for (int mt = 0; mt < 2; mt++){
                uint32_t ad = ab + SWZ((uint32_t)(arow + mt * 16) * 128u + (ks * 16 + acol8) * 2u);
                LDSM4(a[mt][0], a[mt][1], a[mt][2], a[mt][3], ad);
            }
            #pragma unroll
            for (int np = 0; np < 4; np++){
                uint32_t b0, b1, b2, b3;
                uint32_t bd = bb + SWZ((uint32_t)(brow + np * 16) * 128u + (ks * 16 + bcol8) * 2u);
                LDSM4(b0, b1, b2, b3, bd);
                #pragma unroll
                for (int mt = 0; mt < 2; mt++){
                    MMA4(acc[mt][np * 2],     a[mt], b0, b1);
                    MMA4(acc[mt][np * 2 + 1], a[mt], b2, b3);
                }
            }
        }
        __syncthreads();
    }

    // epilogue
    #pragma unroll
    for (int mt = 0; mt < 2; mt++){
        #pragma unroll
        for (int nt = 0; nt < 8; nt++){
            ll r0 = bm + wm * 32 + mt * 16 + (lane >> 2);
            ll col = bn + wn * 64 + nt * 8 + (lane & 3) * 2;
            float bx = 0.f, by = 0.f;
            if (bias){ bx = bias[col]; by = bias[col + 1]; }
            *(float2*)&C[r0 * ldC + col] =
                make_float2(acc[mt][nt][0] + bx, acc[mt][nt][1] + by);
            *(float2*)&C[(r0 + 8) * ldC + col] =
                make_float2(acc[mt][nt][2] + bx, acc[mt][nt][3] + by);
        }
    }
}

// ============================================================================
// ctx GEMM (unchanged from R4, known-correct)
// ============================================================================
__global__ __launch_bounds__(256) void ctx_hmma(
    const float* __restrict__ att, const __half* __restrict__ vh,
    float* __restrict__ ctxf)
{
    extern __shared__ char sm[];
    const int tid = threadIdx.x, lane = tid & 31, wid = tid >> 5;
    const int wm = wid >> 1, wn = wid & 1;
    const int z = blockIdx.z;
    const ll bm = (ll)blockIdx.y * 128;
    const uint32_t sbase = smem_u32(sm);

    float acc[2][4][4];
    #pragma unroll
    for (int i = 0; i < 2; i++)
        #pragma unroll
        for (int j = 0; j < 4; j++)
            #pragma unroll
            for (int k = 0; k < 4; k++) acc[i][j][k] = 0.f;

    const int row = tid >> 1, hf = tid & 1;
    const float* ap = att + ((ll)z * Sc + bm + row) * Sc + hf * 32;
    const int vsel = tid >> 7, vr = (tid >> 1) & 63, vhf = tid & 1;
    const __half* vp = vh + ((ll)z * 64 + vr) * 2048 + vsel * 1024 + vhf * 32;

    const int arow = wm * 32 + (lane & 7) + ((lane >> 3) & 1) * 8;
    const int acol8 = ((lane >> 4) & 1) * 8;
    const int brow = wn * 32 + (lane & 7) + ((lane >> 4) & 1) * 8;
    const int bcol8 = ((lane >> 3) & 1) * 8;

    for (int c = 0; c < 16; c++){
        __syncthreads();
        #pragma unroll
        for (int j = 0; j < 4; j++){
            float4 x0 = *(const float4*)(ap + c * 64 + j * 8);
            float4 x1 = *(const float4*)(ap + c * 64 + j * 8 + 4);
            float f[8] = {x0.x, x0.y, x0.z, x0.w, x1.x, x1.y, x1.z, x1.w};
            float h[8], l[8];
            #pragma unroll
            for (int e = 0; e < 8; e++){
                __half hh = __float2half_rn(f[e]);
                h[e] = __half2float(hh);
                l[e] = f[e] - h[e];
            }
            uint4 Hv, Lv;
            Hv.x = pack2h(h[0], h[1]); Hv.y = pack2h(h[2], h[3]);
            Hv.z = pack2h(h[4], h[5]); Hv.w = pack2h(h[6], h[7]);
            Lv.x = pack2h(l[0], l[1]); Lv.y = pack2h(l[2], l[3]);
            Lv.z = pack2h(l[4], l[5]); Lv.w = pack2h(l[6], l[7]);
            uint32_t sw = SWZ((uint32_t)row * 128u + hf * 64u + j * 16u);
            *(uint4*)(sm + sw) = Hv;
            *(uint4*)(sm + 16384 + sw) = Lv;
        }
        {
            char* dst = sm + 32768 + vsel * 8192;
            #pragma unroll
            for (int j = 0; j < 4; j++){
                float4 v = *(const float4*)(vp + c * 64 + j * 8);
                uint32_t sw = SWZ((uint32_t)vr * 128u + vhf * 64u + j * 16u);
                *(float4*)(dst + sw) = v;
            }
        }
        __syncthreads();

        const uint32_t ah = sbase, al = sbase + 16384u;
        const uint32_t bh = sbase + 32768u, bl = sbase + 40960u;
        #pragma unroll
        for (int ks = 0; ks < 4; ks++){
            uint32_t Ah[2][4], Al[2][4];
            #pragma unroll
            for (int mt = 0; mt < 2; mt++){
                uint32_t off = SWZ((uint32_t)(arow + mt * 16) * 128u + (ks * 16 + acol8) * 2u);
                LDSM4(Ah[mt][0], Ah[mt][1], Ah[mt][2], Ah[mt][3], ah + off);
                LDSM4(Al[mt][0], Al[mt][1], Al[mt][2], Al[mt][3], al + off);
            }
            #pragma unroll
            for (int np = 0; np < 2; np++){
                uint32_t off = SWZ((uint32_t)(brow + np * 16) * 128u + (ks * 16 + bcol8) * 2u);
                uint32_t h0, h1, h2, h3, l0, l1, l2, l3;
                LDSM4(h0, h1, h2, h3, bh + off);
                LDSM4(l0, l1, l2, l3, bl + off);
                #pragma unroll
                for (int mt = 0; mt < 2; mt++){
                    MMA4(acc[mt][np * 2],     Ah[mt], h0, h1);
                    MMA4(acc[mt][np * 2 + 1], Ah[mt], h2, h3);
                    MMA4(acc[mt][np * 2],     Ah[mt], l0, l1);
                    MMA4(acc[mt][np * 2 + 1], Ah[mt], l2, l3);
                    MMA4(acc[mt][np * 2],     Al[mt], h0, h1);
                    MMA4(acc[mt][np * 2 + 1], Al[mt], h2, h3);
                }
            }
        }
    }

    const int b = z >> 4, h = z & 15;
    #pragma unroll
    for (int mt = 0; mt < 2; mt++){
        #pragma unroll
        for (int nt = 0; nt < 4; nt++){
            ll r = bm + wm * 32 + mt * 16 + (lane >> 2);
            ll col = (ll)h * 64 + wn * 32 + nt * 8 + (lane & 3) * 2;
            *(float2*)&ctxf[((ll)b * Sc + r) * Dc + col] =
                make_float2(acc[mt][nt][0], acc[mt][nt][1]);
            *(float2*)&ctxf[((ll)b * Sc + r + 8) * Dc + col] =
                make_float2(acc[mt][nt][2], acc[mt][nt][3]);
        }
    }
}

// ============================================================================
// Conversions (fp16 split) — unchanged
// ============================================================================
__global__ void splitA_dup(const float* __restrict__ X, __half* __restrict__ O, int Cdim)
{
    ll e = ((ll)blockIdx.x * blockDim.x + threadIdx.x) * 2;
    ll r = e / Cdim; int c = (int)(e % Cdim);
    float2 v = *(const float2*)(X + e);
    __half hx = __float2half_rn(v.x), hy = __float2half_rn(v.y);
    uint32_t H; { __half2 t = __halves2half2(hx, hy); H = *(uint32_t*)&t; }
    uint32_t L = pack2h(v.x - __half2float(hx), v.y - __half2float(hy));
    __half* o = O + r * (ll)(3 * Cdim) + c;
    *(uint32_t*)(o) = H; *(uint32_t*)(o + Cdim) = H; *(uint32_t*)(o + 2 * Cdim) = L;
}
__global__ void splitB(const float* __restrict__ X, ll ldin,
                       __half* __restrict__ O, ll ldout, int Cdim)
{
    ll e = ((ll)blockIdx.x * blockDim.x + threadIdx.x) * 2;
    ll r = e / Cdim; int c = (int)(e % Cdim);
    float2 v = *(const float2*)(X + r * ldin + c);
    __half hx = __float2half_rn(v.x), hy = __float2half_rn(v.y);
    uint32_t H; { __half2 t = __halves2half2(hx, hy); H = *(uint32_t*)&t; }
    uint32_t L = pack2h(v.x - __half2float(hx), v.y - __half2float(hy));
    __half* o = O + r * ldout + c;
    *(uint32_t*)(o) = H; *(uint32_t*)(o + Cdim) = L; *(uint32_t*)(o + 2 * Cdim) = H;
}
__global__ void head_split(const float* __restrict__ X, __half* __restrict__ O,
                           int offDup, int offLo, float scale)
{
    ll e = ((ll)blockIdx.x * blockDim.x + threadIdx.x) * 2;
    ll tok = e >> 10; int d = (int)(e & 1023);
    int h = d >> 6, dk = d & 63;
    ll b = tok >> 10, s = tok & 1023;
    float2 v = *(const float2*)(X + e);
    v.x *= scale; v.y *= scale;
    __half hx = __float2half_rn(v.x), hy = __float2half_rn(v.y);
    uint32_t H; { __half2 t = __halves2half2(hx, hy); H = *(uint32_t*)&t; }
    uint32_t L = pack2h(v.x - __half2float(hx), v.y - __half2float(hy));
    __half* o = O + (((ll)(b * 16 + h) * 1024 + s) * 192) + dk;
    *(uint32_t*)(o) = H; *(uint32_t*)(o + offDup) = H; *(uint32_t*)(o + offLo) = L;
}
__global__ void vT_split(const float* __restrict__ X, __half* __restrict__ O)
{
    ll e = (ll)blockIdx.x * blockDim.x + threadIdx.x;
    int kk = (int)(e & 1023); ll t = e >> 10;
    int dk = (int)(t & 63);   ll t2 = t >> 6;
    int h = (int)(t2 & 15);   int b = (int)(t2 >> 4);
    float x = X[((ll)b * 1024 + kk) * 1024 + h * 64 + dk];
    __half hx = __float2half_rn(x);
    ll o = (((ll)(b * 16 + h) * 64 + dk) * 2048) + kk;
    O[o] = hx;
    O[o + 1024] = __float2half_rn(x - __half2float(hx));
}

// ===== softmax (known-correct) =====
__global__ void __launch_bounds__(256) softmax_kernel(
    float* __restrict__ att, const unsigned int* __restrict__ mask)
{
    const int row = blockIdx.x;
    const int q = row & (Sc - 1);
    const int bh = row >> 10, b = bh >> 4;
    float* p = att + (size_t)row * Sc;
    const int tid = threadIdx.x;
    if (mask[b * Sc + q] != 0u){
        const float u = 1.0f / (float)Sc;
        ((float4*)p)[tid] = make_float4(u, u, u, u);
        return;
    }
    __shared__ float sh[16];
    float4 x = ((const float4*)p)[tid];
    float mx = fmaxf(fmaxf(x.x, x.y), fmaxf(x.z, x.w));
    #pragma unroll
    for (int o = 16; o; o >>= 1) mx = fmaxf(mx, __shfl_xor_sync(0xffffffffu, mx, o));
    const int w = tid >> 5, l = tid & 31;
    if (l == 0) sh[w] = mx;
    __syncthreads();
    if (tid < 32){
        float v = (l < 8) ? sh[l] : -3.4e38f;
        #pragma unroll
        for (int o = 4; o; o >>= 1) v = fmaxf(v, __shfl_xor_sync(0xffffffffu, v, o));
        if (l == 0) sh[8] = v;
    }
    __syncthreads();
    mx = sh[8];
    float e0 = __expf(x.x - mx), e1 = __expf(x.y - mx);
    float e2 = __expf(x.z - mx), e3 = __expf(x.w - mx);
    float s = e0 + e1 + e2 + e3;
    #pragma unroll
    for (int o = 16; o; o >>= 1) s += __shfl_xor_sync(0xffffffffu, s, o);
    if (l == 0) sh[w] = s;
    __syncthreads();
    if (tid < 32){
        float v = (l < 8) ? sh[l] : 0.f;
        #pragma unroll
        for (int o = 4; o; o >>= 1) v += __shfl_xor_sync(0xffffffffu, v, o);
        if (l == 0) sh[9] = v;
    }
    __syncthreads();
    const float inv = 1.0f / sh[9];
    ((float4*)p)[tid] = make_float4(e0 * inv, e1 * inv, e2 * inv, e3 * inv);
}

extern "C" void kernel_launch(void* const* d_in, const int* in_sizes, int n_in,
                              void* d_out, int out_size)
{
    (void)in_sizes; (void)n_in; (void)out_size;
    const float* key   = (const float*)d_in[0];
    const float* query = (const float*)d_in[1];
    const float* value = (const float*)d_in[2];
    const unsigned int* mask = (const unsigned int*)d_in[3];
    const float* Wk = (const float*)d_in[4];
    const float* bk = (const float*)d_in[5];
    const float* Wq = (const float*)d_in[6];
    const float* bq = (const float*)d_in[7];
    const float* Wv = (const float*)d_in[8];
    const float* bv = (const float*)d_in[9];
    const float* Wp = (const float*)d_in[10];
    const float* bp = (const float*)d_in[11];

    float* att = (float*)d_out;
    float* outp = (float*)d_out + (size_t)BHc * Sc * Sc;

    __half *in3,*W3,*wp,*qh,*kh,*vhp,*ctxs;
    float *F3,*ctxf;
    cudaGetSymbolAddress((void**)&in3, g_in3);
    cudaGetSymbolAddress((void**)&W3, g_W3);
    cudaGetSymbolAddress((void**)&wp, g_Wps);
    cudaGetSymbolAddress((void**)&qh, g_qh);
    cudaGetSymbolAddress((void**)&kh, g_kh);
    cudaGetSymbolAddress((void**)&vhp, g_vh);
    cudaGetSymbolAddress((void**)&ctxs, g_ctxs);
    cudaGetSymbolAddress((void**)&F3, g_F3);
    cudaGetSymbolAddress((void**)&ctxf, g_ctxf);

    const ll IN_Z = (ll)Mrows * 3 * Dc;   // per-z stride in in3
    const ll W_Z  = (ll)Dc * 3 * Dc;
    const ll F_Z  = (ll)Mrows * Dc;
    float* Qf = F3;
    float* Kf = F3 + F_Z;
    float* Vf = F3 + 2 * F_Z;

    cudaFuncSetAttribute(gemm_hmma, cudaFuncAttributeMaxDynamicSharedMemorySize, 98304);
    cudaFuncSetAttribute(ctx_hmma, cudaFuncAttributeMaxDynamicSharedMemorySize, 49152);
    const int GS = 98304, CS = 49152;

    // splits (z-order: 0=query 1=key 2=value)
    splitA_dup<<<(Mrows*Dc/2)/256, 256>>>(query, in3,            Dc);
    splitA_dup<<<(Mrows*Dc/2)/256, 256>>>(key,   in3 + IN_Z,     Dc);
    splitA_dup<<<(Mrows*Dc/2)/256, 256>>>(value, in3 + 2*IN_Z,   Dc);
    splitB<<<(Dc*Dc/2)/256, 256>>>(Wq, Dc, W3,          3*Dc, Dc);
    splitB<<<(Dc*Dc/2)/256, 256>>>(Wk, Dc, W3 + W_Z,    3*Dc, Dc);
    splitB<<<(Dc*Dc/2)/256, 256>>>(Wv, Dc, W3 + 2*W_Z,  3*Dc, Dc);
    splitB<<<(Dc*Dc/2)/256, 256>>>(Wp,      2*Dc, wp,        6*Dc, Dc);
    splitB<<<(Dc*Dc/2)/256, 256>>>(Wp + Dc, 2*Dc, wp + 3*Dc, 6*Dc, Dc);

    // all three projections in one batched launch (z=3)
    gemm_hmma<<<dim3(Dc/128, Mrows/128, 3), 256, GS>>>(
        in3, 3*Dc, IN_Z, W3, 3*Dc, W_Z, 48,
        in3, 3*Dc, W3, 3*Dc, 0,
        F3, Dc, F_Z, bq, bk, bv);

    // per-head splits
    head_split<<<(Mrows*Dc/2)/256, 256>>>(Qf, qh, 64, 128, 0.125f);   // A pattern
    head_split<<<(Mrows*Dc/2)/256, 256>>>(Kf, kh, 128, 64, 1.0f);     // B pattern
    vT_split<<<(int)(((ll)BHc*DKc*Sc)/256), 256>>>(Vf, vhp);

    // scores (batched over 128 heads)
    gemm_hmma<<<dim3(Sc/128, Sc/128, BHc), 256, GS>>>(
        qh, 192, (ll)Sc*192, kh, 192, (ll)Sc*192, 3,
        qh, 192, kh, 192, 0,
        att, Sc, (ll)Sc*Sc, nullptr, nullptr, nullptr);

    softmax_kernel<<<BHc*Sc, 256>>>(att, mask);

    ctx_hmma<<<dim3(1, Sc/128, BHc), 256, CS>>>(att, vhp, ctxf);

    splitA_dup<<<(Mrows*Dc/2)/256, 256>>>(ctxf, ctxs, Dc);

    // output projection: concat(query, ctx) @ Wp^T + bp
    gemm_hmma<<<dim3(Dc/128, Mrows/128, 1), 256, GS>>>(
        in3, 3*Dc, 0, wp, 6*Dc, 0, 48,
        ctxs, 3*Dc, wp + 3*Dc, 6*Dc, 48,
        outp, Dc, 0, bp, bp, bp);
}